// round 3
// baseline (speedup 1.0000x reference)
#include <cuda_runtime.h>

#define NN   50000
#define NE   500000
#define HID  128
#define NGR  64
#define REP  32
#define UNB  32   // nodes per update block

// ---------------- device scratch (no allocations allowed) ----------------
__device__ __align__(16) float g_pa[NN*HID];        // x @ (Wn Wm_a)
__device__ __align__(16) float g_pb[NN*HID];        // x @ (Wn Wm_b)
__device__ __align__(16) float g_agg[NN*HID];       // message sums (atomic)
__device__ __align__(16) float g_cnt[NN];           // in-degree counts
__device__ __align__(16) float g_gsum[REP*NGR*HID]; // replicated graph sums
__device__ __align__(16) float g_gcnt[REP*NGR];
__device__ __align__(16) float g_WA[16*HID];        // Wn @ Wm_a
__device__ __align__(16) float g_WB[16*HID];        // Wn @ Wm_b
__device__ __align__(16) float g_WE2[8*HID];        // We @ Wm_c
__device__ __align__(16) float g_WU1[16*HID];       // Wn @ Wu_top
__device__ __align__(16) float g_bconst[HID];       // bn@Wm_a + bn@Wm_b + be@Wm_c + bm
__device__ __align__(16) float g_bup[HID];          // bn@Wu_top + bu
__device__ int g_row[NE];
__device__ int g_col[NE];
__device__ int g_batchi[NN];
__device__ int g_flag64;

// ---------------- helpers ----------------
__device__ __forceinline__ void red_f32(float* p, float v) {
    asm volatile("red.global.add.f32 [%0], %1;" :: "l"(p), "f"(v) : "memory");
}
__device__ __forceinline__ void red_v4(float* p, float4 v) {
    asm volatile("red.global.add.v4.f32 [%0], {%1,%2,%3,%4};"
                 :: "l"(p), "f"(v.x), "f"(v.y), "f"(v.z), "f"(v.w) : "memory");
}
__device__ __forceinline__ unsigned long long splat2(float w) {
    unsigned long long r;
    asm("mov.b64 %0, {%1, %1};" : "=l"(r) : "r"(__float_as_uint(w)));
    return r;
}
__device__ __forceinline__ void fma_f32x2(unsigned long long& d,
                                          unsigned long long a,
                                          unsigned long long b) {
    asm("fma.rn.f32x2 %0, %1, %2, %0;" : "+l"(d) : "l"(a), "l"(b));
}

// ---------------- 0: zero accumulators ----------------
__global__ void k_zero() {
    int i = blockIdx.x * blockDim.x + threadIdx.x;
    int stride = gridDim.x * blockDim.x;
    float4 z = {0.f, 0.f, 0.f, 0.f};
    for (int j = i; j < NN*HID/4;      j += stride) ((float4*)g_agg )[j] = z;
    for (int j = i; j < NN/4;          j += stride) ((float4*)g_cnt )[j] = z;
    for (int j = i; j < REP*NGR*HID/4; j += stride) ((float4*)g_gsum)[j] = z;
    for (int j = i; j < REP*NGR/4;     j += stride) ((float4*)g_gcnt)[j] = z;
}

// ---------------- 1: detect int64 vs int32 indices ----------------
// If edge_index is int64 (values < 2^31, >=0), the int32 view has all
// odd words == 0. 32 random node ids being all zero: P ~ (1/50000)^32.
__global__ void k_detect(const int* __restrict__ ei32) {
    int t = threadIdx.x;
    int v = ei32[2*t + 1];
    unsigned m = __ballot_sync(0xffffffffu, v != 0);
    if (t == 0) g_flag64 = (m == 0u) ? 1 : 0;
}

// ---------------- 2: convert indices to int32 scratch ----------------
__global__ void k_convert(const void* __restrict__ ei, const void* __restrict__ batch) {
    int i = blockIdx.x * blockDim.x + threadIdx.x;
    const bool f = (g_flag64 != 0);
    if (i < 2*NE) {
        int v = f ? (int)((const long long*)ei)[i] : ((const int*)ei)[i];
        if (i < NE) g_row[i] = v; else g_col[i - NE] = v;
    }
    if (i < NN) {
        g_batchi[i] = f ? (int)((const long long*)batch)[i] : ((const int*)batch)[i];
    }
}

// ---------------- 3: fold weights (tiny GEMMs) ----------------
__global__ void k_prep(const float* __restrict__ Wn, const float* __restrict__ bn,
                       const float* __restrict__ We, const float* __restrict__ be,
                       const float* __restrict__ Wm, const float* __restrict__ bm,
                       const float* __restrict__ Wu, const float* __restrict__ bu) {
    int c = threadIdx.x;  // 128 threads, one output column each
    float accA[16], accB[16], accU[16], accE[8];
    #pragma unroll
    for (int i = 0; i < 16; i++) { accA[i] = 0.f; accB[i] = 0.f; accU[i] = 0.f; }
    #pragma unroll
    for (int j = 0; j < 8; j++) accE[j] = 0.f;
    float bc = bm[c];
    float bup = bu[c];
    for (int k = 0; k < HID; k++) {
        float wma = Wm[k*HID + c];
        float wmb = Wm[(HID + k)*HID + c];
        float wu  = Wu[k*HID + c];          // Wu_top
        float bnk = bn[k];
        bc  += bnk * (wma + wmb);
        bup += bnk * wu;
        #pragma unroll
        for (int i = 0; i < 16; i++) {
            float wn = Wn[i*HID + k];
            accA[i] += wn * wma;
            accB[i] += wn * wmb;
            accU[i] += wn * wu;
        }
    }
    for (int k = 0; k < HID; k++) {
        float wmc = Wm[(2*HID + k)*HID + c];
        bc += be[k] * wmc;
        #pragma unroll
        for (int j = 0; j < 8; j++) accE[j] += We[j*HID + k] * wmc;
    }
    #pragma unroll
    for (int i = 0; i < 16; i++) {
        g_WA [i*HID + c] = accA[i];
        g_WB [i*HID + c] = accB[i];
        g_WU1[i*HID + c] = accU[i];
    }
    #pragma unroll
    for (int j = 0; j < 8; j++) g_WE2[j*HID + c] = accE[j];
    g_bconst[c] = bc;
    g_bup[c]    = bup;
}

// ---------------- 4: per-node projections pa, pb ----------------
__global__ __launch_bounds__(256) void k_node(const float* __restrict__ x) {
    __shared__ float4 sWA[16*32], sWB[16*32];
    int t = threadIdx.x;
    for (int j = t; j < 16*32; j += 256) {
        sWA[j] = ((const float4*)g_WA)[j];
        sWB[j] = ((const float4*)g_WB)[j];
    }
    __syncthreads();
    int warp = t >> 5, lane = t & 31;
    int n = blockIdx.x * 8 + warp;
    if (n >= NN) return;
    const float4* xr = (const float4*)(x + n*16);
    float xv[16];
    #pragma unroll
    for (int q = 0; q < 4; q++) {
        float4 v = xr[q];
        xv[4*q+0] = v.x; xv[4*q+1] = v.y; xv[4*q+2] = v.z; xv[4*q+3] = v.w;
    }
    float4 a = {0,0,0,0}, b = {0,0,0,0};
    #pragma unroll
    for (int i = 0; i < 16; i++) {
        float4 wa = sWA[i*32 + lane];
        float4 wb = sWB[i*32 + lane];
        a.x += xv[i]*wa.x; a.y += xv[i]*wa.y; a.z += xv[i]*wa.z; a.w += xv[i]*wa.w;
        b.x += xv[i]*wb.x; b.y += xv[i]*wb.y; b.z += xv[i]*wb.z; b.w += xv[i]*wb.w;
    }
    ((float4*)g_pa)[n*32 + lane] = a;
    ((float4*)g_pb)[n*32 + lane] = b;
}

// ---------------- 5: edge kernel — one warp per edge ----------------
__global__ __launch_bounds__(256) void k_edge(const float* __restrict__ ea) {
    __shared__ float4 sWE[8*32];
    __shared__ float4 sbc[32];
    __shared__ float  sea[8*8];
    __shared__ int    srow[8], scol[8];
    int t = threadIdx.x;
    int e0 = blockIdx.x * 8;
    sWE[t] = ((const float4*)g_WE2)[t];          // 256 entries, 256 threads
    if (t < 64) sea[t] = ea[(long long)e0*8 + t];
    if (t < 8)  { srow[t] = g_row[e0 + t]; scol[t] = g_col[e0 + t]; }
    if (t < 32) sbc[t] = ((const float4*)g_bconst)[t];
    __syncthreads();

    int warp = t >> 5, lane = t & 31;
    int row = srow[warp], col = scol[warp];
    float4 m  = ((const float4*)g_pa)[row*32 + lane];   // coalesced (row warp-uniform)
    float4 bv = ((const float4*)g_pb)[col*32 + lane];
    m.x += bv.x; m.y += bv.y; m.z += bv.z; m.w += bv.w;
    #pragma unroll
    for (int j = 0; j < 8; j++) {
        float ej = sea[warp*8 + j];
        float4 w = sWE[j*32 + lane];
        m.x += ej*w.x; m.y += ej*w.y; m.z += ej*w.z; m.w += ej*w.w;
    }
    float4 bc = sbc[lane];
    m.x = fmaxf(m.x + bc.x, 0.f);
    m.y = fmaxf(m.y + bc.y, 0.f);
    m.z = fmaxf(m.z + bc.z, 0.f);
    m.w = fmaxf(m.w + bc.w, 0.f);
    red_v4(&g_agg[col*HID + lane*4], m);
    if (lane == 0) red_f32(&g_cnt[col], 1.0f);
}

// ---------------- 6: node update + graph pooling ----------------
__global__ __launch_bounds__(128) void k_update(const float* __restrict__ x,
                                                const float* __restrict__ Wu) {
    __shared__ float saggT[HID][UNB + 4];   // [k][n], pad 36 for bank spread, 8B-align pairs
    __shared__ float sxT[16][UNB + 2];      // [i][n], pad 34
    __shared__ float sinv[UNB];
    __shared__ int   sbatch[UNB];
    int t  = threadIdx.x;                   // thread = channel c
    int n0 = blockIdx.x * UNB;

    if (t < UNB) {
        int node = n0 + t;
        float cv = (node < NN) ? g_cnt[node] : 0.f;
        sinv[t]   = 1.f / fmaxf(cv, 1.f);
        sbatch[t] = (node < NN) ? g_batchi[node] : 0;
    }
    __syncthreads();
    for (int n = 0; n < UNB; n++) {
        int node = n0 + n;
        saggT[t][n] = (node < NN) ? g_agg[node*HID + t] * sinv[n] : 0.f;
    }
    for (int idx = t; idx < 16*UNB; idx += 128) {
        int n = idx & 31, i = idx >> 5;
        int node = n0 + n;
        sxT[i][n] = (node < NN) ? x[node*16 + i] : 0.f;
    }
    __syncthreads();

    const int c = t;
    unsigned long long acc2[UNB/2];         // packed (node 2p, node 2p+1), channel c
    #pragma unroll
    for (int p = 0; p < UNB/2; p++) acc2[p] = 0ULL;

    #pragma unroll
    for (int i = 0; i < 16; i++) {
        unsigned long long w2 = splat2(g_WU1[i*HID + c]);
        #pragma unroll
        for (int p = 0; p < UNB/2; p++) {
            unsigned long long a2 = *(const unsigned long long*)&sxT[i][2*p];
            fma_f32x2(acc2[p], a2, w2);
        }
    }
    for (int k = 0; k < HID; k++) {
        unsigned long long w2 = splat2(Wu[(HID + k)*HID + c]);   // Wu_bot, L1-resident
        #pragma unroll
        for (int p = 0; p < UNB/2; p++) {
            unsigned long long a2 = *(const unsigned long long*)&saggT[k][2*p];
            fma_f32x2(acc2[p], a2, w2);
        }
    }

    float bupv = g_bup[c];
    int   rep  = blockIdx.x & (REP - 1);
    float* gsbase = &g_gsum[rep*NGR*HID];
    int   cur = sbatch[0];
    float sum = 0.f;
    #pragma unroll
    for (int p = 0; p < UNB/2; p++) {
        float hv[2];
        hv[0] = __uint_as_float((unsigned)(acc2[p] & 0xffffffffULL));
        hv[1] = __uint_as_float((unsigned)(acc2[p] >> 32));
        #pragma unroll
        for (int q = 0; q < 2; q++) {
            int n = 2*p + q;
            int node = n0 + n;
            if (node < NN) {
                float h = fmaxf(hv[q] + bupv, 0.f);
                int b = sbatch[n];                 // warp-uniform
                if (b != cur) {
                    red_f32(gsbase + cur*HID + c, sum);
                    cur = b; sum = 0.f;
                }
                sum += h;
            }
        }
    }
    red_f32(gsbase + cur*HID + c, sum);

    if (t < UNB) {
        int node = n0 + t;
        if (node < NN) red_f32(&g_gcnt[rep*NGR + sbatch[t]], 1.0f);
    }
}

// ---------------- 7: readout MLP ----------------
__global__ __launch_bounds__(128) void k_final(const float* __restrict__ Wr1,
                                               const float* __restrict__ br1,
                                               const float* __restrict__ Wr2,
                                               const float* __restrict__ br2,
                                               float* __restrict__ out) {
    __shared__ float sg[HID];
    __shared__ float sred[4];
    int g = blockIdx.x, t = threadIdx.x;
    float s = 0.f;
    for (int r = 0; r < REP; r++) s += g_gsum[r*NGR*HID + g*HID + t];
    float gc = 0.f;
    for (int r = 0; r < REP; r++) gc += g_gcnt[r*NGR + g];
    sg[t] = s / fmaxf(gc, 1.f);
    __syncthreads();
    float acc = br1[t];
    for (int k = 0; k < HID; k++) acc += sg[k] * Wr1[k*HID + t];
    acc = fmaxf(acc, 0.f);
    float v = acc * Wr2[t];
    #pragma unroll
    for (int o = 16; o > 0; o >>= 1) v += __shfl_down_sync(0xffffffffu, v, o);
    if ((t & 31) == 0) sred[t >> 5] = v;
    __syncthreads();
    if (t == 0) out[g] = sred[0] + sred[1] + sred[2] + sred[3] + br2[0];
}

// ---------------- launch ----------------
extern "C" void kernel_launch(void* const* d_in, const int* in_sizes, int n_in,
                              void* d_out, int out_size) {
    const float* x     = (const float*)d_in[0];
    const float* ea    = (const float*)d_in[1];
    const void*  ei    = d_in[2];
    const void*  batch = d_in[3];
    const float* Wn  = (const float*)d_in[4];
    const float* bn  = (const float*)d_in[5];
    const float* We  = (const float*)d_in[6];
    const float* be  = (const float*)d_in[7];
    const float* Wm  = (const float*)d_in[8];
    const float* bm  = (const float*)d_in[9];
    const float* Wu  = (const float*)d_in[10];
    const float* bu  = (const float*)d_in[11];
    const float* Wr1 = (const float*)d_in[12];
    const float* br1 = (const float*)d_in[13];
    const float* Wr2 = (const float*)d_in[14];
    const float* br2 = (const float*)d_in[15];
    float* out = (float*)d_out;

    k_zero   <<<512, 1024>>>();
    k_detect <<<1, 32>>>((const int*)ei);
    k_convert<<<(2*NE + 1023)/1024, 1024>>>(ei, batch);
    k_prep   <<<1, 128>>>(Wn, bn, We, be, Wm, bm, Wu, bu);
    k_node   <<<(NN + 7)/8, 256>>>(x);
    k_edge   <<<NE/8, 256>>>(ea);
    k_update <<<(NN + UNB - 1)/UNB, 128>>>(x, Wu);
    k_final  <<<NGR, 128>>>(Wr1, br1, Wr2, br2, out);
}

// round 4
// speedup vs baseline: 1.3717x; 1.3717x over previous
#include <cuda_runtime.h>

#define NN   50000
#define NE   500000
#define HID  128
#define NGR  64
#define REP  32
#define UNB  32   // nodes per update block

// ---------------- device scratch (no allocations allowed) ----------------
__device__ __align__(16) float g_pa[NN*HID];        // x @ (Wn Wm_a)
__device__ __align__(16) float g_pb[NN*HID];        // x @ (Wn Wm_b)
__device__ __align__(16) float g_agg[NN*HID];       // message sums (atomic)
__device__ __align__(16) float g_cnt[NN];           // in-degree counts
__device__ __align__(16) float g_gsum[REP*NGR*HID]; // replicated graph sums
__device__ __align__(16) float g_gcnt[REP*NGR];
__device__ __align__(16) float g_WA[16*HID];        // Wn @ Wm_a
__device__ __align__(16) float g_WB[16*HID];        // Wn @ Wm_b
__device__ __align__(16) float g_WE2[8*HID];        // We @ Wm_c
__device__ __align__(16) float g_WU1[16*HID];       // Wn @ Wu_top
__device__ __align__(16) float g_bconst[HID];       // bn@Wm_a + bn@Wm_b + be@Wm_c + bm
__device__ __align__(16) float g_bup[HID];          // bn@Wu_top + bu
__device__ int g_row[NE];
__device__ int g_col[NE];
__device__ int g_batchi[NN];
__device__ int g_flag64;

// ---------------- helpers ----------------
__device__ __forceinline__ void red_f32(float* p, float v) {
    asm volatile("red.global.add.f32 [%0], %1;" :: "l"(p), "f"(v) : "memory");
}
__device__ __forceinline__ void red_v4(float* p, float4 v) {
    asm volatile("red.global.add.v4.f32 [%0], {%1,%2,%3,%4};"
                 :: "l"(p), "f"(v.x), "f"(v.y), "f"(v.z), "f"(v.w) : "memory");
}
__device__ __forceinline__ unsigned long long splat2(float w) {
    unsigned long long r;
    asm("mov.b64 %0, {%1, %1};" : "=l"(r) : "r"(__float_as_uint(w)));
    return r;
}
__device__ __forceinline__ void fma_f32x2(unsigned long long& d,
                                          unsigned long long a,
                                          unsigned long long b) {
    asm("fma.rn.f32x2 %0, %1, %2, %0;" : "+l"(d) : "l"(a), "l"(b));
}

// ---------------- 0: zero accumulators ----------------
__global__ void k_zero() {
    int i = blockIdx.x * blockDim.x + threadIdx.x;
    int stride = gridDim.x * blockDim.x;
    float4 z = {0.f, 0.f, 0.f, 0.f};
    for (int j = i; j < NN*HID/4;      j += stride) ((float4*)g_agg )[j] = z;
    for (int j = i; j < NN/4;          j += stride) ((float4*)g_cnt )[j] = z;
    for (int j = i; j < REP*NGR*HID/4; j += stride) ((float4*)g_gsum)[j] = z;
    for (int j = i; j < REP*NGR/4;     j += stride) ((float4*)g_gcnt)[j] = z;
}

// ---------------- 1: detect int64 vs int32 indices ----------------
__global__ void k_detect(const int* __restrict__ ei32) {
    int t = threadIdx.x;
    int v = ei32[2*t + 1];
    unsigned m = __ballot_sync(0xffffffffu, v != 0);
    if (t == 0) g_flag64 = (m == 0u) ? 1 : 0;
}

// ---------------- 2: convert indices to int32 scratch ----------------
__global__ void k_convert(const void* __restrict__ ei, const void* __restrict__ batch) {
    int i = blockIdx.x * blockDim.x + threadIdx.x;
    const bool f = (g_flag64 != 0);
    if (i < 2*NE) {
        int v = f ? (int)((const long long*)ei)[i] : ((const int*)ei)[i];
        if (i < NE) g_row[i] = v; else g_col[i - NE] = v;
    }
    if (i < NN) {
        g_batchi[i] = f ? (int)((const long long*)batch)[i] : ((const int*)batch)[i];
    }
}

// ---------------- 3: fold weights — 57 blocks, one output row each ----------------
// blocks 0..15  : g_WA  row i  = Wn[i,:] @ Wm[0:128,:]
// blocks 16..31 : g_WB  row i  = Wn[i,:] @ Wm[128:256,:]
// blocks 32..47 : g_WU1 row i  = Wn[i,:] @ Wu[0:128,:]
// blocks 48..55 : g_WE2 row j  = We[j,:] @ Wm[256:384,:]
// block  56     : biases
__global__ __launch_bounds__(128) void k_prep(
        const float* __restrict__ Wn, const float* __restrict__ bn,
        const float* __restrict__ We, const float* __restrict__ be,
        const float* __restrict__ Wm, const float* __restrict__ bm,
        const float* __restrict__ Wu, const float* __restrict__ bu) {
    const int c = threadIdx.x;
    const int b = blockIdx.x;

    if (b < 48) {
        const int grp = b >> 4;
        const int i   = b & 15;
        const float* Wl = Wn + i*HID;
        const float* Wr;
        float* out;
        if      (grp == 0) { Wr = Wm;           out = g_WA;  }
        else if (grp == 1) { Wr = Wm + HID*HID; out = g_WB;  }
        else               { Wr = Wu;           out = g_WU1; }
        float a0 = 0.f, a1 = 0.f, a2 = 0.f, a3 = 0.f;
        #pragma unroll 8
        for (int k = 0; k < HID; k += 4) {
            a0 += Wl[k+0] * Wr[(k+0)*HID + c];
            a1 += Wl[k+1] * Wr[(k+1)*HID + c];
            a2 += Wl[k+2] * Wr[(k+2)*HID + c];
            a3 += Wl[k+3] * Wr[(k+3)*HID + c];
        }
        out[i*HID + c] = (a0 + a1) + (a2 + a3);
    } else if (b < 56) {
        const int j = b - 48;
        const float* Wl = We + j*HID;
        const float* Wr = Wm + 2*HID*HID;
        float a0 = 0.f, a1 = 0.f, a2 = 0.f, a3 = 0.f;
        #pragma unroll 8
        for (int k = 0; k < HID; k += 4) {
            a0 += Wl[k+0] * Wr[(k+0)*HID + c];
            a1 += Wl[k+1] * Wr[(k+1)*HID + c];
            a2 += Wl[k+2] * Wr[(k+2)*HID + c];
            a3 += Wl[k+3] * Wr[(k+3)*HID + c];
        }
        g_WE2[j*HID + c] = (a0 + a1) + (a2 + a3);
    } else {
        float bc  = bm[c];
        float bup = bu[c];
        float b0 = 0.f, b1 = 0.f, b2 = 0.f, u0 = 0.f;
        #pragma unroll 4
        for (int k = 0; k < HID; k++) {
            float bnk = bn[k];
            b0 += bnk   * Wm[k*HID + c];
            b1 += bnk   * Wm[(HID + k)*HID + c];
            b2 += be[k] * Wm[(2*HID + k)*HID + c];
            u0 += bnk   * Wu[k*HID + c];
        }
        g_bconst[c] = bc + b0 + b1 + b2;
        g_bup[c]    = bup + u0;
    }
}

// ---------------- 4: per-node projections pa, pb ----------------
__global__ __launch_bounds__(256) void k_node(const float* __restrict__ x) {
    __shared__ float4 sWA[16*32], sWB[16*32];
    int t = threadIdx.x;
    for (int j = t; j < 16*32; j += 256) {
        sWA[j] = ((const float4*)g_WA)[j];
        sWB[j] = ((const float4*)g_WB)[j];
    }
    __syncthreads();
    int warp = t >> 5, lane = t & 31;
    int n = blockIdx.x * 8 + warp;
    if (n >= NN) return;
    const float4* xr = (const float4*)(x + n*16);
    float xv[16];
    #pragma unroll
    for (int q = 0; q < 4; q++) {
        float4 v = xr[q];
        xv[4*q+0] = v.x; xv[4*q+1] = v.y; xv[4*q+2] = v.z; xv[4*q+3] = v.w;
    }
    float4 a = {0,0,0,0}, b = {0,0,0,0};
    #pragma unroll
    for (int i = 0; i < 16; i++) {
        float4 wa = sWA[i*32 + lane];
        float4 wb = sWB[i*32 + lane];
        a.x += xv[i]*wa.x; a.y += xv[i]*wa.y; a.z += xv[i]*wa.z; a.w += xv[i]*wa.w;
        b.x += xv[i]*wb.x; b.y += xv[i]*wb.y; b.z += xv[i]*wb.z; b.w += xv[i]*wb.w;
    }
    ((float4*)g_pa)[n*32 + lane] = a;
    ((float4*)g_pb)[n*32 + lane] = b;
}

// ---------------- 5: edge kernel — one warp per edge ----------------
__global__ __launch_bounds__(256) void k_edge(const float* __restrict__ ea) {
    __shared__ float4 sWE[8*32];
    __shared__ float4 sbc[32];
    __shared__ float  sea[8*8];
    __shared__ int    srow[8], scol[8];
    int t = threadIdx.x;
    int e0 = blockIdx.x * 8;
    sWE[t] = ((const float4*)g_WE2)[t];          // 256 entries, 256 threads
    if (t < 64) sea[t] = ea[(long long)e0*8 + t];
    if (t < 8)  { srow[t] = g_row[e0 + t]; scol[t] = g_col[e0 + t]; }
    if (t < 32) sbc[t] = ((const float4*)g_bconst)[t];
    __syncthreads();

    int warp = t >> 5, lane = t & 31;
    int row = srow[warp], col = scol[warp];
    float4 m  = ((const float4*)g_pa)[row*32 + lane];   // coalesced (row warp-uniform)
    float4 bv = ((const float4*)g_pb)[col*32 + lane];
    m.x += bv.x; m.y += bv.y; m.z += bv.z; m.w += bv.w;
    #pragma unroll
    for (int j = 0; j < 8; j++) {
        float ej = sea[warp*8 + j];
        float4 w = sWE[j*32 + lane];
        m.x += ej*w.x; m.y += ej*w.y; m.z += ej*w.z; m.w += ej*w.w;
    }
    float4 bc = sbc[lane];
    m.x = fmaxf(m.x + bc.x, 0.f);
    m.y = fmaxf(m.y + bc.y, 0.f);
    m.z = fmaxf(m.z + bc.z, 0.f);
    m.w = fmaxf(m.w + bc.w, 0.f);
    red_v4(&g_agg[col*HID + lane*4], m);
    if (lane == 0) red_f32(&g_cnt[col], 1.0f);
}

// ---------------- 6: node update + graph pooling ----------------
__global__ __launch_bounds__(128) void k_update(const float* __restrict__ x,
                                                const float* __restrict__ Wu) {
    __shared__ float saggT[HID][UNB + 4];   // [k][n]
    __shared__ float sxT[16][UNB + 2];      // [i][n]
    __shared__ float sinv[UNB];
    __shared__ int   sbatch[UNB];
    int t  = threadIdx.x;                   // thread = channel c
    int n0 = blockIdx.x * UNB;

    if (t < UNB) {
        int node = n0 + t;
        float cv = (node < NN) ? g_cnt[node] : 0.f;
        sinv[t]   = 1.f / fmaxf(cv, 1.f);
        sbatch[t] = (node < NN) ? g_batchi[node] : 0;
    }
    __syncthreads();
    for (int n = 0; n < UNB; n++) {
        int node = n0 + n;
        saggT[t][n] = (node < NN) ? g_agg[node*HID + t] * sinv[n] : 0.f;
    }
    for (int idx = t; idx < 16*UNB; idx += 128) {
        int n = idx & 31, i = idx >> 5;
        int node = n0 + n;
        sxT[i][n] = (node < NN) ? x[node*16 + i] : 0.f;
    }
    __syncthreads();

    const int c = t;
    unsigned long long acc2[UNB/2];         // packed (node 2p, node 2p+1), channel c
    #pragma unroll
    for (int p = 0; p < UNB/2; p++) acc2[p] = 0ULL;

    #pragma unroll
    for (int i = 0; i < 16; i++) {
        unsigned long long w2 = splat2(g_WU1[i*HID + c]);
        #pragma unroll
        for (int p = 0; p < UNB/2; p++) {
            unsigned long long a2 = *(const unsigned long long*)&sxT[i][2*p];
            fma_f32x2(acc2[p], a2, w2);
        }
    }
    for (int k = 0; k < HID; k++) {
        unsigned long long w2 = splat2(Wu[(HID + k)*HID + c]);   // Wu_bot, L1-resident
        #pragma unroll
        for (int p = 0; p < UNB/2; p++) {
            unsigned long long a2 = *(const unsigned long long*)&saggT[k][2*p];
            fma_f32x2(acc2[p], a2, w2);
        }
    }

    float bupv = g_bup[c];
    int   rep  = blockIdx.x & (REP - 1);
    float* gsbase = &g_gsum[rep*NGR*HID];
    int   cur = sbatch[0];
    float sum = 0.f;
    #pragma unroll
    for (int p = 0; p < UNB/2; p++) {
        float hv[2];
        hv[0] = __uint_as_float((unsigned)(acc2[p] & 0xffffffffULL));
        hv[1] = __uint_as_float((unsigned)(acc2[p] >> 32));
        #pragma unroll
        for (int q = 0; q < 2; q++) {
            int n = 2*p + q;
            int node = n0 + n;
            if (node < NN) {
                float h = fmaxf(hv[q] + bupv, 0.f);
                int b = sbatch[n];                 // warp-uniform
                if (b != cur) {
                    red_f32(gsbase + cur*HID + c, sum);
                    cur = b; sum = 0.f;
                }
                sum += h;
            }
        }
    }
    red_f32(gsbase + cur*HID + c, sum);

    if (t < UNB) {
        int node = n0 + t;
        if (node < NN) red_f32(&g_gcnt[rep*NGR + sbatch[t]], 1.0f);
    }
}

// ---------------- 7: readout MLP ----------------
__global__ __launch_bounds__(128) void k_final(const float* __restrict__ Wr1,
                                               const float* __restrict__ br1,
                                               const float* __restrict__ Wr2,
                                               const float* __restrict__ br2,
                                               float* __restrict__ out) {
    __shared__ float sg[HID];
    __shared__ float sred[4];
    int g = blockIdx.x, t = threadIdx.x;
    float s = 0.f;
    for (int r = 0; r < REP; r++) s += g_gsum[r*NGR*HID + g*HID + t];
    float gc = 0.f;
    for (int r = 0; r < REP; r++) gc += g_gcnt[r*NGR + g];
    sg[t] = s / fmaxf(gc, 1.f);
    __syncthreads();
    float acc = br1[t];
    for (int k = 0; k < HID; k++) acc += sg[k] * Wr1[k*HID + t];
    acc = fmaxf(acc, 0.f);
    float v = acc * Wr2[t];
    #pragma unroll
    for (int o = 16; o > 0; o >>= 1) v += __shfl_down_sync(0xffffffffu, v, o);
    if ((t & 31) == 0) sred[t >> 5] = v;
    __syncthreads();
    if (t == 0) out[g] = sred[0] + sred[1] + sred[2] + sred[3] + br2[0];
}

// ---------------- launch ----------------
extern "C" void kernel_launch(void* const* d_in, const int* in_sizes, int n_in,
                              void* d_out, int out_size) {
    const float* x     = (const float*)d_in[0];
    const float* ea    = (const float*)d_in[1];
    const void*  ei    = d_in[2];
    const void*  batch = d_in[3];
    const float* Wn  = (const float*)d_in[4];
    const float* bn  = (const float*)d_in[5];
    const float* We  = (const float*)d_in[6];
    const float* be  = (const float*)d_in[7];
    const float* Wm  = (const float*)d_in[8];
    const float* bm  = (const float*)d_in[9];
    const float* Wu  = (const float*)d_in[10];
    const float* bu  = (const float*)d_in[11];
    const float* Wr1 = (const float*)d_in[12];
    const float* br1 = (const float*)d_in[13];
    const float* Wr2 = (const float*)d_in[14];
    const float* br2 = (const float*)d_in[15];
    float* out = (float*)d_out;

    k_zero   <<<512, 1024>>>();
    k_detect <<<1, 32>>>((const int*)ei);
    k_convert<<<(2*NE + 1023)/1024, 1024>>>(ei, batch);
    k_prep   <<<57, 128>>>(Wn, bn, We, be, Wm, bm, Wu, bu);
    k_node   <<<(NN + 7)/8, 256>>>(x);
    k_edge   <<<NE/8, 256>>>(ea);
    k_update <<<(NN + UNB - 1)/UNB, 128>>>(x, Wu);
    k_final  <<<NGR, 128>>>(Wr1, br1, Wr2, br2, out);
}